// round 10
// baseline (speedup 1.0000x reference)
#include <cuda_runtime.h>
#include <cstdint>

#define NQ      8192
#define NR      16384
#define KNN     8
#define NCHUNK  32
#define RPC     (NR / NCHUNK)     // 512 refs per chunk
#define PPC     (RPC / 2)         // 256 packed pairs (8 KB tile)
#define QPB     128               // threads per block
#define QT      4                 // queries per thread
#define QPG     (QPB * QT)        // 512 queries per block
#define QBLK    (NQ / QPG)        // 16 -> grid 512 for p1a/p1c
#define NSL     32                // slices per chunk
#define PPSL    (PPC / NSL)       // 8 pairs per slice (16 refs)
#define CAP     96                // compact candidate cap (PAIRS) per query; E ~ 9

typedef unsigned long long ull;

__device__ float      g_t2[2 * NCHUNK * NQ];        // per-chunk sorted-2 slice-minima
__device__ float      g_tau[NQ];                    // global per-query threshold
__device__ int        g_pcnt[NQ];                   // per-query candidate count
__device__ ulonglong2 g_ckey[(size_t)NQ * CAP];     // compact candidate pairs (12.6 MB)

__device__ __forceinline__ ull fma2(ull a, ull b, ull c) {
    ull d; asm("fma.rn.f32x2 %0, %1, %2, %3;" : "=l"(d) : "l"(a), "l"(b), "l"(c));
    return d;
}
__device__ __forceinline__ ull pk2(float lo, float hi) {
    ull r; asm("mov.b64 %0, {%1, %2};" : "=l"(r) : "f"(lo), "f"(hi));
    return r;
}
__device__ __forceinline__ void up2(float& lo, float& hi, ull v) {
    asm("mov.b64 {%0, %1}, %2;" : "=f"(lo), "=f"(hi) : "l"(v));
}
__device__ __forceinline__ unsigned f2ord(float f) {
    unsigned b = __float_as_uint(f);
    return (b & 0x80000000u) ? ~b : (b | 0x80000000u);
}

// Stage tile: pack {x01,y01,z01,w01}, w = r^2 with the reference's rounding.
__device__ __forceinline__ void stage_tile(ulonglong4* tile, const float* __restrict__ ref,
                                           int rbase) {
    for (int p = threadIdx.x; p < PPC; p += QPB) {
        const float2* a = (const float2*)(ref + (size_t)(rbase + 2 * p) * 3);
        float2 u0 = __ldg(a), u1 = __ldg(a + 1), u2 = __ldg(a + 2);
        float x0 = u0.x, y0 = u0.y, z0 = u1.x, x1 = u1.y, y1 = u2.x, z1 = u2.y;
        float w0 = __fadd_rn(__fadd_rn(__fmul_rn(x0, x0), __fmul_rn(y0, y0)), __fmul_rn(z0, z0));
        float w1 = __fadd_rn(__fadd_rn(__fmul_rn(x1, x1), __fmul_rn(y1, y1)), __fmul_rn(z1, z1));
        ulonglong4 v;
        v.x = pk2(x0, x1); v.y = pk2(y0, y1); v.z = pk2(z0, z1); v.w = pk2(w0, w1);
        tile[p] = v;
    }
}

// p1a: per (query-group, chunk): slice minima -> per-chunk sorted-2. Branchless.
__global__ __launch_bounds__(QPB) void knn_p1a(const float* __restrict__ qry,
                                               const float* __restrict__ ref) {
    __shared__ ulonglong4 tile[PPC];
    const int chunk = blockIdx.x % NCHUNK;
    const int qb    = (blockIdx.x / NCHUNK) * QPG + threadIdx.x;
    stage_tile(tile, ref, chunk * RPC);

    ull m2x[QT], m2y[QT], m2z[QT];
#pragma unroll
    for (int k = 0; k < QT; ++k) {
        int qi = qb + k * QPB;
        float qx = qry[qi * 3 + 0], qy = qry[qi * 3 + 1], qz = qry[qi * 3 + 2];
        m2x[k] = pk2(-2.0f * qx, -2.0f * qx);
        m2y[k] = pk2(-2.0f * qy, -2.0f * qy);
        m2z[k] = pk2(-2.0f * qz, -2.0f * qz);
    }
    const float INF = __int_as_float(0x7f800000);
    float t0[QT], t1[QT];
#pragma unroll
    for (int k = 0; k < QT; ++k) { t0[k] = INF; t1[k] = INF; }
    __syncthreads();

    for (int sl = 0; sl < NSL; ++sl) {
        float a0[QT], a1[QT];
#pragma unroll
        for (int k = 0; k < QT; ++k) { a0[k] = INF; a1[k] = INF; }
        const ulonglong4* base = tile + sl * PPSL;
#pragma unroll
        for (int it = 0; it < PPSL; ++it) {
            ulonglong4 v = base[it];            // warp-uniform -> LDS broadcast
#pragma unroll
            for (int k = 0; k < QT; ++k) {
                ull s2 = fma2(m2x[k], v.x, fma2(m2y[k], v.y, fma2(m2z[k], v.z, v.w)));
                float s0, s1; up2(s0, s1, s2);
                a0[k] = fminf(a0[k], s0); a1[k] = fminf(a1[k], s1);
            }
        }
#pragma unroll
        for (int k = 0; k < QT; ++k) {
            float m  = fminf(a0[k], a1[k]);
            float hi = fmaxf(t0[k], m);
            t0[k] = fminf(t0[k], m);
            t1[k] = fminf(t1[k], hi);
        }
    }
#pragma unroll
    for (int k = 0; k < QT; ++k) {
        int qi = qb + k * QPB;
        g_t2[(chunk * 2 + 0) * NQ + qi] = t0[k];
        g_t2[(chunk * 2 + 1) * NQ + qi] = t1[k];
    }
}

// p1b: fold 64 kept slice minima -> tau* (8th smallest); zero candidate counts.
__global__ void knn_p1b() {
    int qi = blockIdx.x * blockDim.x + threadIdx.x;
    if (qi >= NQ) return;
    const float INF = __int_as_float(0x7f800000);
    float t[KNN];
#pragma unroll
    for (int j = 0; j < KNN; ++j) t[j] = INF;
#pragma unroll 4
    for (int s = 0; s < 2 * NCHUNK; ++s) {
        float c = g_t2[s * NQ + qi];
#pragma unroll
        for (int j = 0; j < KNN; ++j) { float lo = fminf(t[j], c), hi = fmaxf(t[j], c); t[j] = lo; c = hi; }
    }
    g_tau[qi] = t[KNN - 1];
    g_pcnt[qi] = 0;                       // reset for p1c (graph-replay safe: same stream order)
}

// p1c: scan chunk; append pairs with min(s0,s1) <= tau* into the per-query
// compact buffer (atomicAdd slot). Keys unique -> merge is order-independent,
// so atomic ordering does not affect the final (deterministic) top-8.
__global__ __launch_bounds__(QPB) void knn_p1c(const float* __restrict__ qry,
                                               const float* __restrict__ ref) {
    __shared__ ulonglong4 tile[PPC];
    const int chunk = blockIdx.x % NCHUNK;
    const int rbase = chunk * RPC;
    const int qb    = (blockIdx.x / NCHUNK) * QPG + threadIdx.x;
    stage_tile(tile, ref, rbase);

    ull m2x[QT], m2y[QT], m2z[QT];
    float tau[QT];
    int qidx[QT];
#pragma unroll
    for (int k = 0; k < QT; ++k) {
        int qi = qb + k * QPB;
        qidx[k] = qi;
        float qx = qry[qi * 3 + 0], qy = qry[qi * 3 + 1], qz = qry[qi * 3 + 2];
        m2x[k] = pk2(-2.0f * qx, -2.0f * qx);
        m2y[k] = pk2(-2.0f * qy, -2.0f * qy);
        m2z[k] = pk2(-2.0f * qz, -2.0f * qz);
        tau[k] = g_tau[qi];
    }
    __syncthreads();

#pragma unroll 4
    for (int p = 0; p < PPC; ++p) {
        ulonglong4 v = tile[p];
        unsigned ri = (unsigned)(rbase + 2 * p);
        bool hit = false;
        float s0v[QT], s1v[QT];
#pragma unroll
        for (int k = 0; k < QT; ++k) {
            ull s2 = fma2(m2x[k], v.x, fma2(m2y[k], v.y, fma2(m2z[k], v.z, v.w)));
            up2(s0v[k], s1v[k], s2);
            hit |= (fminf(s0v[k], s1v[k]) <= tau[k]);
        }
        if (__any_sync(0xffffffffu, hit)) {       // rare (~14% of iterations)
#pragma unroll
            for (int k = 0; k < QT; ++k) {
                if (fminf(s0v[k], s1v[k]) <= tau[k]) {
                    int slot = atomicAdd(&g_pcnt[qidx[k]], 1);
                    if (slot >= CAP) slot = CAP - 1;        // memory safety (never expected)
                    ulonglong2 kp;
                    kp.x = ((ull)__float_as_uint(s0v[k]) << 32) | ri;
                    kp.y = ((ull)__float_as_uint(s1v[k]) << 32) | (ri + 1);
                    g_ckey[(size_t)qidx[k] * CAP + slot] = kp;
                }
            }
        }
    }
}

// p2: merge ~9 contiguous candidate pairs per query; emit top-8 indices as floats.
__global__ void knn_p2(float* __restrict__ out) {
    int qi = blockIdx.x * blockDim.x + threadIdx.x;
    if (qi >= NQ) return;

    ull best[KNN];
#pragma unroll
    for (int j = 0; j < KNN; ++j) best[j] = ~0ull;

    int n = g_pcnt[qi];
    if (n > CAP) n = CAP;
    const ulonglong2* buf = g_ckey + (size_t)qi * CAP;
    for (int j = 0; j < n; ++j) {
        ulonglong2 kp = buf[j];
#pragma unroll 2
        for (int h = 0; h < 2; ++h) {
            ull raw = h ? kp.y : kp.x;
            ull k = ((ull)f2ord(__uint_as_float((unsigned)(raw >> 32))) << 32)
                    | (raw & 0xffffffffu);
            if (k < best[KNN - 1]) {
#pragma unroll
                for (int m = 0; m < KNN; ++m) {
                    if (k < best[m]) { ull tmp = best[m]; best[m] = k; k = tmp; }
                }
            }
        }
    }
#pragma unroll
    for (int j = 0; j < KNN; ++j)
        out[qi * KNN + j] = (float)(int)(best[j] & 0xffffffffu);
}

extern "C" void kernel_launch(void* const* d_in, const int* in_sizes, int n_in,
                              void* d_out, int out_size) {
    (void)n_in; (void)out_size;
    const float* q;
    const float* r;
    if (in_sizes[0] < in_sizes[1]) { q = (const float*)d_in[0]; r = (const float*)d_in[1]; }
    else                           { q = (const float*)d_in[1]; r = (const float*)d_in[0]; }

    knn_p1a<<<QBLK * NCHUNK, QPB>>>(q, r);
    knn_p1b<<<NQ / 128, 128>>>();
    knn_p1c<<<QBLK * NCHUNK, QPB>>>(q, r);
    knn_p2<<<NQ / 128, 128>>>((float*)d_out);
}

// round 11
// speedup vs baseline: 1.5875x; 1.5875x over previous
#include <cuda_runtime.h>
#include <cstdint>

#define NQ      8192
#define NR      16384
#define KNN     8
#define NCHUNK  64
#define RPC     (NR / NCHUNK)     // 256 refs per chunk
#define PPC     (RPC / 2)         // 128 packed pairs (4 KB tile)
#define QPB     128               // threads per block
#define QT      4                 // queries per thread
#define QPG     (QPB * QT)        // 512 queries per block
#define QBLK    (NQ / QPG)        // 16 -> grid 1024 for p1a/p1c
#define NSL     16                // slices per chunk
#define PPSL    (PPC / NSL)       // 8 pairs per slice (16 refs)
#define CAP     96                // compact candidate cap (PAIRS) per query; E ~ 10

typedef unsigned long long ull;

__device__ float      g_t2[2 * NCHUNK * NQ];        // per-chunk sorted-2 slice-minima
__device__ float      g_tau[NQ];                    // global per-query threshold
__device__ int        g_pcnt[NQ];                   // per-query candidate count
__device__ ulonglong2 g_ckey[(size_t)NQ * CAP];     // compact candidate pairs

__device__ __forceinline__ ull fma2(ull a, ull b, ull c) {
    ull d; asm("fma.rn.f32x2 %0, %1, %2, %3;" : "=l"(d) : "l"(a), "l"(b), "l"(c));
    return d;
}
__device__ __forceinline__ ull pk2(float lo, float hi) {
    ull r; asm("mov.b64 %0, {%1, %2};" : "=l"(r) : "f"(lo), "f"(hi));
    return r;
}
__device__ __forceinline__ void up2(float& lo, float& hi, ull v) {
    asm("mov.b64 {%0, %1}, %2;" : "=f"(lo), "=f"(hi) : "l"(v));
}
__device__ __forceinline__ unsigned f2ord(float f) {
    unsigned b = __float_as_uint(f);
    return (b & 0x80000000u) ? ~b : (b | 0x80000000u);
}

// Stage tile: pack {x01,y01,z01,w01}, w = r^2 with the reference's rounding.
__device__ __forceinline__ void stage_tile(ulonglong4* tile, const float* __restrict__ ref,
                                           int rbase) {
    for (int p = threadIdx.x; p < PPC; p += QPB) {
        const float2* a = (const float2*)(ref + (size_t)(rbase + 2 * p) * 3);
        float2 u0 = __ldg(a), u1 = __ldg(a + 1), u2 = __ldg(a + 2);
        float x0 = u0.x, y0 = u0.y, z0 = u1.x, x1 = u1.y, y1 = u2.x, z1 = u2.y;
        float w0 = __fadd_rn(__fadd_rn(__fmul_rn(x0, x0), __fmul_rn(y0, y0)), __fmul_rn(z0, z0));
        float w1 = __fadd_rn(__fadd_rn(__fmul_rn(x1, x1), __fmul_rn(y1, y1)), __fmul_rn(z1, z1));
        ulonglong4 v;
        v.x = pk2(x0, x1); v.y = pk2(y0, y1); v.z = pk2(z0, z1); v.w = pk2(w0, w1);
        tile[p] = v;
    }
}

// p1a: per (query-group, chunk): slice minima -> per-chunk sorted-2. Branchless.
__global__ __launch_bounds__(QPB) void knn_p1a(const float* __restrict__ qry,
                                               const float* __restrict__ ref) {
    __shared__ ulonglong4 tile[PPC];
    const int chunk = blockIdx.x % NCHUNK;
    const int qb    = (blockIdx.x / NCHUNK) * QPG + threadIdx.x;
    stage_tile(tile, ref, chunk * RPC);

    ull m2x[QT], m2y[QT], m2z[QT];
#pragma unroll
    for (int k = 0; k < QT; ++k) {
        int qi = qb + k * QPB;
        float qx = qry[qi * 3 + 0], qy = qry[qi * 3 + 1], qz = qry[qi * 3 + 2];
        m2x[k] = pk2(-2.0f * qx, -2.0f * qx);
        m2y[k] = pk2(-2.0f * qy, -2.0f * qy);
        m2z[k] = pk2(-2.0f * qz, -2.0f * qz);
    }
    const float INF = __int_as_float(0x7f800000);
    float t0[QT], t1[QT];
#pragma unroll
    for (int k = 0; k < QT; ++k) { t0[k] = INF; t1[k] = INF; }
    __syncthreads();

    for (int sl = 0; sl < NSL; ++sl) {
        float a0[QT], a1[QT];
#pragma unroll
        for (int k = 0; k < QT; ++k) { a0[k] = INF; a1[k] = INF; }
        const ulonglong4* base = tile + sl * PPSL;
#pragma unroll
        for (int it = 0; it < PPSL; ++it) {
            ulonglong4 v = base[it];            // warp-uniform -> LDS broadcast
#pragma unroll
            for (int k = 0; k < QT; ++k) {
                ull s2 = fma2(m2x[k], v.x, fma2(m2y[k], v.y, fma2(m2z[k], v.z, v.w)));
                float s0, s1; up2(s0, s1, s2);
                a0[k] = fminf(a0[k], s0); a1[k] = fminf(a1[k], s1);
            }
        }
#pragma unroll
        for (int k = 0; k < QT; ++k) {
            float m  = fminf(a0[k], a1[k]);
            float hi = fmaxf(t0[k], m);
            t0[k] = fminf(t0[k], m);
            t1[k] = fminf(t1[k], hi);
        }
    }
#pragma unroll
    for (int k = 0; k < QT; ++k) {
        int qi = qb + k * QPB;
        g_t2[(chunk * 2 + 0) * NQ + qi] = t0[k];
        g_t2[(chunk * 2 + 1) * NQ + qi] = t1[k];
    }
}

// p1b: fold 128 kept slice minima -> tau* (8th smallest); zero candidate counts.
__global__ void knn_p1b() {
    int qi = blockIdx.x * blockDim.x + threadIdx.x;
    if (qi >= NQ) return;
    const float INF = __int_as_float(0x7f800000);
    float t[KNN];
#pragma unroll
    for (int j = 0; j < KNN; ++j) t[j] = INF;
#pragma unroll 4
    for (int s = 0; s < 2 * NCHUNK; ++s) {
        float c = g_t2[s * NQ + qi];
#pragma unroll
        for (int j = 0; j < KNN; ++j) { float lo = fminf(t[j], c), hi = fmaxf(t[j], c); t[j] = lo; c = hi; }
    }
    g_tau[qi] = t[KNN - 1];
    g_pcnt[qi] = 0;                       // reset for p1c (same-stream order -> replay safe)
}

// p1c: scan chunk; append pairs with min(s0,s1) <= tau* into the per-query
// compact buffer (atomicAdd slot). Keys unique -> final top-8 order-independent.
__global__ __launch_bounds__(QPB) void knn_p1c(const float* __restrict__ qry,
                                               const float* __restrict__ ref) {
    __shared__ ulonglong4 tile[PPC];
    const int chunk = blockIdx.x % NCHUNK;
    const int rbase = chunk * RPC;
    const int qb    = (blockIdx.x / NCHUNK) * QPG + threadIdx.x;
    stage_tile(tile, ref, rbase);

    ull m2x[QT], m2y[QT], m2z[QT];
    float tau[QT];
    int qidx[QT];
#pragma unroll
    for (int k = 0; k < QT; ++k) {
        int qi = qb + k * QPB;
        qidx[k] = qi;
        float qx = qry[qi * 3 + 0], qy = qry[qi * 3 + 1], qz = qry[qi * 3 + 2];
        m2x[k] = pk2(-2.0f * qx, -2.0f * qx);
        m2y[k] = pk2(-2.0f * qy, -2.0f * qy);
        m2z[k] = pk2(-2.0f * qz, -2.0f * qz);
        tau[k] = g_tau[qi];
    }
    __syncthreads();

#pragma unroll 4
    for (int p = 0; p < PPC; ++p) {
        ulonglong4 v = tile[p];
        unsigned ri = (unsigned)(rbase + 2 * p);
        bool hit = false;
        float s0v[QT], s1v[QT];
#pragma unroll
        for (int k = 0; k < QT; ++k) {
            ull s2 = fma2(m2x[k], v.x, fma2(m2y[k], v.y, fma2(m2z[k], v.z, v.w)));
            up2(s0v[k], s1v[k], s2);
            hit |= (fminf(s0v[k], s1v[k]) <= tau[k]);
        }
        if (__any_sync(0xffffffffu, hit)) {       // rare (~14% of iterations)
#pragma unroll
            for (int k = 0; k < QT; ++k) {
                if (fminf(s0v[k], s1v[k]) <= tau[k]) {
                    int slot = atomicAdd(&g_pcnt[qidx[k]], 1);
                    if (slot >= CAP) slot = CAP - 1;        // safety (never expected)
                    ulonglong2 kp;
                    kp.x = ((ull)__float_as_uint(s0v[k]) << 32) | ri;
                    kp.y = ((ull)__float_as_uint(s1v[k]) << 32) | (ri + 1);
                    g_ckey[(size_t)qidx[k] * CAP + slot] = kp;
                }
            }
        }
    }
}

// p2: merge ~10 contiguous candidate pairs per query; emit top-8 indices as floats.
__global__ void knn_p2(float* __restrict__ out) {
    int qi = blockIdx.x * blockDim.x + threadIdx.x;
    if (qi >= NQ) return;

    ull best[KNN];
#pragma unroll
    for (int j = 0; j < KNN; ++j) best[j] = ~0ull;

    int n = g_pcnt[qi];
    if (n > CAP) n = CAP;
    const ulonglong2* buf = g_ckey + (size_t)qi * CAP;

    int j = 0;
    for (; j + 2 <= n; j += 2) {            // unroll-2: issue both loads before use (MLP)
        ulonglong2 kpa = buf[j], kpb = buf[j + 1];
        ull raws[4] = {kpa.x, kpa.y, kpb.x, kpb.y};
#pragma unroll
        for (int h = 0; h < 4; ++h) {
            ull k = ((ull)f2ord(__uint_as_float((unsigned)(raws[h] >> 32))) << 32)
                    | (raws[h] & 0xffffffffu);
            if (k < best[KNN - 1]) {
#pragma unroll
                for (int m = 0; m < KNN; ++m) {
                    if (k < best[m]) { ull tmp = best[m]; best[m] = k; k = tmp; }
                }
            }
        }
    }
    for (; j < n; ++j) {
        ulonglong2 kp = buf[j];
#pragma unroll 2
        for (int h = 0; h < 2; ++h) {
            ull raw = h ? kp.y : kp.x;
            ull k = ((ull)f2ord(__uint_as_float((unsigned)(raw >> 32))) << 32)
                    | (raw & 0xffffffffu);
            if (k < best[KNN - 1]) {
#pragma unroll
                for (int m = 0; m < KNN; ++m) {
                    if (k < best[m]) { ull tmp = best[m]; best[m] = k; k = tmp; }
                }
            }
        }
    }
#pragma unroll
    for (int j2 = 0; j2 < KNN; ++j2)
        out[qi * KNN + j2] = (float)(int)(best[j2] & 0xffffffffu);
}

extern "C" void kernel_launch(void* const* d_in, const int* in_sizes, int n_in,
                              void* d_out, int out_size) {
    (void)n_in; (void)out_size;
    const float* q;
    const float* r;
    if (in_sizes[0] < in_sizes[1]) { q = (const float*)d_in[0]; r = (const float*)d_in[1]; }
    else                           { q = (const float*)d_in[1]; r = (const float*)d_in[0]; }

    knn_p1a<<<QBLK * NCHUNK, QPB>>>(q, r);
    knn_p1b<<<NQ / 128, 128>>>();
    knn_p1c<<<QBLK * NCHUNK, QPB>>>(q, r);
    knn_p2<<<NQ / 128, 128>>>((float*)d_out);
}

// round 12
// speedup vs baseline: 1.7794x; 1.1208x over previous
#include <cuda_runtime.h>
#include <cstdint>

#define NQ        8192
#define NR        16384
#define KNN       8
#define NCHUNK    64
#define RPC       (NR / NCHUNK)     // 256 refs per chunk
#define PPC       (RPC / 2)         // 128 packed pairs (4 KB tile)
#define QPB       128               // threads per block (p1a)
#define QT        4                 // queries per thread (p1a)
#define QPG       (QPB * QT)        // 512 queries per block
#define QBLK      (NQ / QPG)        // 16 -> grid 1024 for p1a
#define NSL       8                 // slices per chunk (32 refs each)
#define PPSL      (PPC / NSL)       // 16 pairs per slice
#define NSLICES   (NCHUNK * NSL)    // 512 slices total
#define MAXH      24                // hit-slice cap per query (expect 8)
#define MAXK      32                // candidate-key cap per query (expect ~9)

typedef unsigned long long ull;

__device__ float g_smin[(size_t)NQ * NSLICES];   // per (query, slice) minima, 16 MB

__device__ __forceinline__ ull fma2(ull a, ull b, ull c) {
    ull d; asm("fma.rn.f32x2 %0, %1, %2, %3;" : "=l"(d) : "l"(a), "l"(b), "l"(c));
    return d;
}
__device__ __forceinline__ ull pk2(float lo, float hi) {
    ull r; asm("mov.b64 %0, {%1, %2};" : "=l"(r) : "f"(lo), "f"(hi));
    return r;
}
__device__ __forceinline__ void up2(float& lo, float& hi, ull v) {
    asm("mov.b64 {%0, %1}, %2;" : "=f"(lo), "=f"(hi) : "l"(v));
}
__device__ __forceinline__ unsigned f2ord(float f) {
    unsigned b = __float_as_uint(f);
    return (b & 0x80000000u) ? ~b : (b | 0x80000000u);
}

// Stage tile: pack {x01,y01,z01,w01}, w = r^2 (reference rounding, no contraction).
__device__ __forceinline__ void stage_tile(ulonglong4* tile, const float* __restrict__ ref,
                                           int rbase) {
    for (int p = threadIdx.x; p < PPC; p += QPB) {
        const float2* a = (const float2*)(ref + (size_t)(rbase + 2 * p) * 3);
        float2 u0 = __ldg(a), u1 = __ldg(a + 1), u2 = __ldg(a + 2);
        float x0 = u0.x, y0 = u0.y, z0 = u1.x, x1 = u1.y, y1 = u2.x, z1 = u2.y;
        float w0 = __fadd_rn(__fadd_rn(__fmul_rn(x0, x0), __fmul_rn(y0, y0)), __fmul_rn(z0, z0));
        float w1 = __fadd_rn(__fadd_rn(__fmul_rn(x1, x1), __fmul_rn(y1, y1)), __fmul_rn(z1, z1));
        ulonglong4 v;
        v.x = pk2(x0, x1); v.y = pk2(y0, y1); v.z = pk2(z0, z1); v.w = pk2(w0, w1);
        tile[p] = v;
    }
}

// p1a: full scan; store the min of every 32-ref slice per query. Branchless.
__global__ __launch_bounds__(QPB) void knn_p1a(const float* __restrict__ qry,
                                               const float* __restrict__ ref) {
    __shared__ ulonglong4 tile[PPC];
    const int chunk = blockIdx.x % NCHUNK;
    const int qb    = (blockIdx.x / NCHUNK) * QPG + threadIdx.x;
    stage_tile(tile, ref, chunk * RPC);

    ull m2x[QT], m2y[QT], m2z[QT];
#pragma unroll
    for (int k = 0; k < QT; ++k) {
        int qi = qb + k * QPB;
        float qx = qry[qi * 3 + 0], qy = qry[qi * 3 + 1], qz = qry[qi * 3 + 2];
        m2x[k] = pk2(-2.0f * qx, -2.0f * qx);
        m2y[k] = pk2(-2.0f * qy, -2.0f * qy);
        m2z[k] = pk2(-2.0f * qz, -2.0f * qz);
    }
    const float INF = __int_as_float(0x7f800000);
    float sm[QT][NSL];
    __syncthreads();

#pragma unroll
    for (int sl = 0; sl < NSL; ++sl) {
        float a0[QT], a1[QT];
#pragma unroll
        for (int k = 0; k < QT; ++k) { a0[k] = INF; a1[k] = INF; }
        const ulonglong4* base = tile + sl * PPSL;
#pragma unroll
        for (int it = 0; it < PPSL; ++it) {
            ulonglong4 v = base[it];            // warp-uniform -> LDS broadcast
#pragma unroll
            for (int k = 0; k < QT; ++k) {
                ull s2 = fma2(m2x[k], v.x, fma2(m2y[k], v.y, fma2(m2z[k], v.z, v.w)));
                float s0, s1; up2(s0, s1, s2);
                a0[k] = fminf(a0[k], s0); a1[k] = fminf(a1[k], s1);
            }
        }
#pragma unroll
        for (int k = 0; k < QT; ++k) sm[k][sl] = fminf(a0[k], a1[k]);
    }

#pragma unroll
    for (int k = 0; k < QT; ++k) {
        int qi = qb + k * QPB;
        float4* dst = (float4*)(g_smin + (size_t)qi * NSLICES + chunk * NSL);
        dst[0] = make_float4(sm[k][0], sm[k][1], sm[k][2], sm[k][3]);
        dst[1] = make_float4(sm[k][4], sm[k][5], sm[k][6], sm[k][7]);
    }
}

// p1c: warp per query. Fold 512 slice minima -> tau* (bitonic shfl merge),
// gather the ~8 hit slices, collect keys <= tau*, merge, write output.
__global__ __launch_bounds__(256) void knn_p1c(const float* __restrict__ qry,
                                               const float* __restrict__ ref,
                                               float* __restrict__ out) {
    __shared__ int sh_ids[8][MAXH];
    __shared__ ull sh_keys[8][MAXK];
    const int wid  = threadIdx.x >> 5;
    const int lane = threadIdx.x & 31;
    const int qi   = blockIdx.x * 8 + wid;

    // Load this lane's 16 slice minima (2 KB/warp, coalesced float4).
    const float4* sp = (const float4*)(g_smin + (size_t)qi * NSLICES + lane * 16);
    float v[16];
#pragma unroll
    for (int i = 0; i < 4; ++i) {
        float4 f = sp[i];
        v[i * 4 + 0] = f.x; v[i * 4 + 1] = f.y; v[i * 4 + 2] = f.z; v[i * 4 + 3] = f.w;
    }

    // Per-lane sorted-8 (ascending) of its 16 values.
    const float INF = __int_as_float(0x7f800000);
    float t[KNN];
#pragma unroll
    for (int j = 0; j < KNN; ++j) t[j] = INF;
#pragma unroll
    for (int j = 0; j < 16; ++j) {
        float c = v[j];
#pragma unroll
        for (int m = 0; m < KNN; ++m) { float lo = fminf(t[m], c), hi = fmaxf(t[m], c); t[m] = lo; c = hi; }
    }

    // Cross-lane merge: 5 shfl.xor stages; every lane ends with the global sorted-8.
#pragma unroll
    for (int d = 1; d < 32; d <<= 1) {
        float p[KNN];
#pragma unroll
        for (int i = 0; i < KNN; ++i) p[i] = __shfl_xor_sync(0xffffffffu, t[i], d);
        float c[KNN];
#pragma unroll
        for (int i = 0; i < KNN; ++i) c[i] = fminf(t[i], p[KNN - 1 - i]);  // Batcher lower half (bitonic)
        // bitonic sort of 8 (distances 4, 2, 1)
#pragma unroll
        for (int i = 0; i < 4; ++i) { float lo = fminf(c[i], c[i + 4]), hi = fmaxf(c[i], c[i + 4]); c[i] = lo; c[i + 4] = hi; }
#pragma unroll
        for (int g = 0; g < 2; ++g)
#pragma unroll
            for (int i = 0; i < 2; ++i) {
                int a = g * 4 + i, b = a + 2;
                float lo = fminf(c[a], c[b]), hi = fmaxf(c[a], c[b]); c[a] = lo; c[b] = hi;
            }
#pragma unroll
        for (int g = 0; g < 4; ++g) {
            int a = g * 2, b = a + 1;
            float lo = fminf(c[a], c[b]), hi = fmaxf(c[a], c[b]); c[a] = lo; c[b] = hi;
        }
#pragma unroll
        for (int i = 0; i < KNN; ++i) t[i] = c[i];
    }
    const float tau = t[KNN - 1];

    // Gate: ballot-compact ids of slices with min <= tau (expect exactly 8).
    int base = 0;
#pragma unroll
    for (int j = 0; j < 16; ++j) {
        bool p = (v[j] <= tau);
        unsigned m = __ballot_sync(0xffffffffu, p);
        int pre = __popc(m & ((1u << lane) - 1));
        int slot = base + pre;
        if (p && slot < MAXH) sh_ids[wid][slot] = lane * 16 + j;
        base += __popc(m);
    }
    int nhit = (base < MAXH) ? base : MAXH;
    __syncwarp();

    // Query coefficients (scalar; bit-identical rounding to p1a's f32x2 lanes).
    const float qx = qry[qi * 3 + 0];
    const float qy = qry[qi * 3 + 1];
    const float qz = qry[qi * 3 + 2];
    const float m2x = -2.0f * qx, m2y = -2.0f * qy, m2z = -2.0f * qz;

    // Scan hit slices: 1 ref per lane per slice; collect keys with s <= tau.
    int nk = 0;
    for (int h = 0; h < nhit; ++h) {
        int s = sh_ids[wid][h];
        int ridx = s * 32 + lane;
        const float* rp = ref + (size_t)ridx * 3;
        float x = rp[0], y = rp[1], z = rp[2];
        float w = __fadd_rn(__fadd_rn(__fmul_rn(x, x), __fmul_rn(y, y)), __fmul_rn(z, z));
        float sd = __fmaf_rn(m2x, x, __fmaf_rn(m2y, y, __fmaf_rn(m2z, z, w)));
        bool p = (sd <= tau);
        unsigned m = __ballot_sync(0xffffffffu, p);
        int pre = __popc(m & ((1u << lane) - 1));
        int slot = nk + pre;
        if (p && slot < MAXK)
            sh_keys[wid][slot] = ((ull)f2ord(sd) << 32) | (unsigned)ridx;
        nk += __popc(m);
    }
    if (nk > MAXK) nk = MAXK;
    __syncwarp();

    // Lane 0: merge ~9 keys -> top-8, write output indices as floats.
    if (lane == 0) {
        ull best[KNN];
#pragma unroll
        for (int j = 0; j < KNN; ++j) best[j] = ~0ull;
        for (int j = 0; j < nk; ++j) {
            ull k = sh_keys[wid][j];
            if (k < best[KNN - 1]) {
#pragma unroll
                for (int m = 0; m < KNN; ++m) {
                    if (k < best[m]) { ull tmp = best[m]; best[m] = k; k = tmp; }
                }
            }
        }
#pragma unroll
        for (int j = 0; j < KNN; ++j)
            out[qi * KNN + j] = (float)(int)(best[j] & 0xffffffffu);
    }
}

extern "C" void kernel_launch(void* const* d_in, const int* in_sizes, int n_in,
                              void* d_out, int out_size) {
    (void)n_in; (void)out_size;
    const float* q;
    const float* r;
    if (in_sizes[0] < in_sizes[1]) { q = (const float*)d_in[0]; r = (const float*)d_in[1]; }
    else                           { q = (const float*)d_in[1]; r = (const float*)d_in[0]; }

    knn_p1a<<<QBLK * NCHUNK, QPB>>>(q, r);
    knn_p1c<<<NQ / 8, 256>>>(q, r, (float*)d_out);
}

// round 13
// speedup vs baseline: 2.9336x; 1.6486x over previous
#include <cuda_runtime.h>
#include <cstdint>

#define NQ        8192
#define NR        16384
#define KNN       8
#define NCHUNK    64
#define RPC       (NR / NCHUNK)     // 256 refs per chunk
#define PPC       (RPC / 2)         // 128 packed pairs (4 KB tile)
#define QPB       128               // threads per block (p1a)
#define QT        4                 // queries per thread (p1a)
#define QPG       (QPB * QT)        // 512 queries per block
#define QBLK      (NQ / QPG)        // 16 -> grid 1024 for p1a
#define NSL       8                 // slices per chunk (32 refs each)
#define PPSL      (PPC / NSL)       // 16 pairs per slice
#define NSLICES   (NCHUNK * NSL)    // 512 slices total
#define MAXH      28                // hit-slice cap per query (expect ~8)
#define MAXK      40                // candidate-key cap per query (expect ~9)

typedef unsigned long long ull;

__device__ float g_smin[(size_t)NQ * NSLICES];   // per (query, slice) minima, 16 MB

__device__ __forceinline__ ull fma2(ull a, ull b, ull c) {
    ull d; asm("fma.rn.f32x2 %0, %1, %2, %3;" : "=l"(d) : "l"(a), "l"(b), "l"(c));
    return d;
}
__device__ __forceinline__ ull pk2(float lo, float hi) {
    ull r; asm("mov.b64 %0, {%1, %2};" : "=l"(r) : "f"(lo), "f"(hi));
    return r;
}
__device__ __forceinline__ void up2(float& lo, float& hi, ull v) {
    asm("mov.b64 {%0, %1}, %2;" : "=f"(lo), "=f"(hi) : "l"(v));
}
__device__ __forceinline__ unsigned f2ord(float f) {
    unsigned b = __float_as_uint(f);
    return (b & 0x80000000u) ? ~b : (b | 0x80000000u);
}

// Stage tile: pack {x01,y01,z01,w01}, w = r^2 (reference rounding, no contraction).
__device__ __forceinline__ void stage_tile(ulonglong4* tile, const float* __restrict__ ref,
                                           int rbase) {
    for (int p = threadIdx.x; p < PPC; p += QPB) {
        const float2* a = (const float2*)(ref + (size_t)(rbase + 2 * p) * 3);
        float2 u0 = __ldg(a), u1 = __ldg(a + 1), u2 = __ldg(a + 2);
        float x0 = u0.x, y0 = u0.y, z0 = u1.x, x1 = u1.y, y1 = u2.x, z1 = u2.y;
        float w0 = __fadd_rn(__fadd_rn(__fmul_rn(x0, x0), __fmul_rn(y0, y0)), __fmul_rn(z0, z0));
        float w1 = __fadd_rn(__fadd_rn(__fmul_rn(x1, x1), __fmul_rn(y1, y1)), __fmul_rn(z1, z1));
        ulonglong4 v;
        v.x = pk2(x0, x1); v.y = pk2(y0, y1); v.z = pk2(z0, z1); v.w = pk2(w0, w1);
        tile[p] = v;
    }
}

// p1a: full scan; store the min of every 32-ref slice per query. Branchless.
__global__ __launch_bounds__(QPB) void knn_p1a(const float* __restrict__ qry,
                                               const float* __restrict__ ref) {
    __shared__ ulonglong4 tile[PPC];
    const int chunk = blockIdx.x % NCHUNK;
    const int qb    = (blockIdx.x / NCHUNK) * QPG + threadIdx.x;
    stage_tile(tile, ref, chunk * RPC);

    ull m2x[QT], m2y[QT], m2z[QT];
#pragma unroll
    for (int k = 0; k < QT; ++k) {
        int qi = qb + k * QPB;
        float qx = qry[qi * 3 + 0], qy = qry[qi * 3 + 1], qz = qry[qi * 3 + 2];
        m2x[k] = pk2(-2.0f * qx, -2.0f * qx);
        m2y[k] = pk2(-2.0f * qy, -2.0f * qy);
        m2z[k] = pk2(-2.0f * qz, -2.0f * qz);
    }
    const float INF = __int_as_float(0x7f800000);
    float sm[QT][NSL];
    __syncthreads();

#pragma unroll
    for (int sl = 0; sl < NSL; ++sl) {
        float a0[QT], a1[QT];
#pragma unroll
        for (int k = 0; k < QT; ++k) { a0[k] = INF; a1[k] = INF; }
        const ulonglong4* base = tile + sl * PPSL;
#pragma unroll
        for (int it = 0; it < PPSL; ++it) {
            ulonglong4 v = base[it];            // warp-uniform -> LDS broadcast
#pragma unroll
            for (int k = 0; k < QT; ++k) {
                ull s2 = fma2(m2x[k], v.x, fma2(m2y[k], v.y, fma2(m2z[k], v.z, v.w)));
                float s0, s1; up2(s0, s1, s2);
                a0[k] = fminf(a0[k], s0); a1[k] = fminf(a1[k], s1);
            }
        }
#pragma unroll
        for (int k = 0; k < QT; ++k) sm[k][sl] = fminf(a0[k], a1[k]);
    }

#pragma unroll
    for (int k = 0; k < QT; ++k) {
        int qi = qb + k * QPB;
        float4* dst = (float4*)(g_smin + (size_t)qi * NSLICES + chunk * NSL);
        dst[0] = make_float4(sm[k][0], sm[k][1], sm[k][2], sm[k][3]);
        dst[1] = make_float4(sm[k][4], sm[k][5], sm[k][6], sm[k][7]);
    }
}

// p1c: warp per query. Cheap tau (per-lane sorted-2 + 8 extraction rounds),
// gather hit slices, collect keys <= tau, merge, write output.
__global__ __launch_bounds__(256) void knn_p1c(const float* __restrict__ qry,
                                               const float* __restrict__ ref,
                                               float* __restrict__ out) {
    __shared__ int sh_ids[8][MAXH];
    __shared__ ull sh_keys[8][MAXK];
    const int wid  = threadIdx.x >> 5;
    const int lane = threadIdx.x & 31;
    const int qi   = blockIdx.x * 8 + wid;

    // Load this lane's 16 slice minima (2 KB/warp, coalesced float4).
    const float4* sp = (const float4*)(g_smin + (size_t)qi * NSLICES + lane * 16);
    float v[16];
#pragma unroll
    for (int i = 0; i < 4; ++i) {
        float4 f = sp[i];
        v[i * 4 + 0] = f.x; v[i * 4 + 1] = f.y; v[i * 4 + 2] = f.z; v[i * 4 + 3] = f.w;
    }

    // Per-lane sorted-2 of 16 values (t0 <= t1). 64 min/max ops.
    const float INF = __int_as_float(0x7f800000);
    float t0 = INF, t1 = INF;
#pragma unroll
    for (int j = 0; j < 16; ++j) {
        float c  = v[j];
        float lo = fminf(t0, c), hi = fmaxf(t0, c);
        t0 = lo;
        t1 = fminf(t1, hi);
    }

    // 8 extraction rounds: butterfly warp-min of t0; owner lane(s) pop.
    // Ties/truncation only INFLATE tau -> still a correct (conservative) gate.
    float tau = INF;
#pragma unroll
    for (int r = 0; r < KNN; ++r) {
        float m = t0;
#pragma unroll
        for (int d = 16; d >= 1; d >>= 1)
            m = fminf(m, __shfl_xor_sync(0xffffffffu, m, d));
        bool own = (t0 == m);
        t0 = own ? t1 : t0;
        t1 = own ? INF : t1;
        tau = m;                        // nondecreasing; 8th round = gate
    }

    // Gate: ballot-compact ids of slices with min <= tau (expect ~8).
    int base = 0;
#pragma unroll
    for (int j = 0; j < 16; ++j) {
        bool p = (v[j] <= tau);
        unsigned m = __ballot_sync(0xffffffffu, p);
        int pre = __popc(m & ((1u << lane) - 1));
        int slot = base + pre;
        if (p && slot < MAXH) sh_ids[wid][slot] = lane * 16 + j;
        base += __popc(m);
    }
    int nhit = (base < MAXH) ? base : MAXH;
    __syncwarp();

    // Query coefficients (scalar; bit-identical rounding to p1a's f32x2 lanes).
    const float qx = qry[qi * 3 + 0];
    const float qy = qry[qi * 3 + 1];
    const float qz = qry[qi * 3 + 2];
    const float m2x = -2.0f * qx, m2y = -2.0f * qy, m2z = -2.0f * qz;

    // Scan hit slices: 1 ref per lane per slice; collect keys with s <= tau.
    int nk = 0;
    for (int h = 0; h < nhit; ++h) {
        int s = sh_ids[wid][h];
        int ridx = s * 32 + lane;
        const float* rp = ref + (size_t)ridx * 3;
        float x = rp[0], y = rp[1], z = rp[2];
        float w = __fadd_rn(__fadd_rn(__fmul_rn(x, x), __fmul_rn(y, y)), __fmul_rn(z, z));
        float sd = __fmaf_rn(m2x, x, __fmaf_rn(m2y, y, __fmaf_rn(m2z, z, w)));
        bool p = (sd <= tau);
        unsigned m = __ballot_sync(0xffffffffu, p);
        int pre = __popc(m & ((1u << lane) - 1));
        int slot = nk + pre;
        if (p && slot < MAXK)
            sh_keys[wid][slot] = ((ull)f2ord(sd) << 32) | (unsigned)ridx;
        nk += __popc(m);
    }
    if (nk > MAXK) nk = MAXK;
    __syncwarp();

    // Lane 0: merge ~9 keys -> top-8, write output indices as floats.
    if (lane == 0) {
        ull best[KNN];
#pragma unroll
        for (int j = 0; j < KNN; ++j) best[j] = ~0ull;
        for (int j = 0; j < nk; ++j) {
            ull k = sh_keys[wid][j];
            if (k < best[KNN - 1]) {
#pragma unroll
                for (int m = 0; m < KNN; ++m) {
                    if (k < best[m]) { ull tmp = best[m]; best[m] = k; k = tmp; }
                }
            }
        }
#pragma unroll
        for (int j = 0; j < KNN; ++j)
            out[qi * KNN + j] = (float)(int)(best[j] & 0xffffffffu);
    }
}

extern "C" void kernel_launch(void* const* d_in, const int* in_sizes, int n_in,
                              void* d_out, int out_size) {
    (void)n_in; (void)out_size;
    const float* q;
    const float* r;
    if (in_sizes[0] < in_sizes[1]) { q = (const float*)d_in[0]; r = (const float*)d_in[1]; }
    else                           { q = (const float*)d_in[1]; r = (const float*)d_in[0]; }

    knn_p1a<<<QBLK * NCHUNK, QPB>>>(q, r);
    knn_p1c<<<NQ / 8, 256>>>(q, r, (float*)d_out);
}

// round 14
// speedup vs baseline: 3.4442x; 1.1741x over previous
#include <cuda_runtime.h>
#include <cstdint>

#define NQ        8192
#define NR        16384
#define KNN       8
#define NCHUNK    64
#define RPC       (NR / NCHUNK)     // 256 refs per chunk
#define PPC       (RPC / 2)         // 128 packed pairs (4 KB tile)
#define QPB       128               // threads per block (p1a)
#define QT        4                 // queries per thread (p1a)
#define QPG       (QPB * QT)        // 512 queries per block
#define QBLK      (NQ / QPG)        // 16 -> grid 1024 for p1a
#define NSL       8                 // slices per chunk (32 refs each)
#define PPSL      (PPC / NSL)       // 16 pairs per slice
#define NSLICES   (NCHUNK * NSL)    // 512 slices total
#define MAXH      28                // hit-slice cap per query
#define MAXK      32                // candidate-key cap per query (lane-sort width)

typedef unsigned long long ull;

__device__ float g_smin[(size_t)NQ * NSLICES];   // per (query, slice) minima, 16 MB

__device__ __forceinline__ ull fma2(ull a, ull b, ull c) {
    ull d; asm("fma.rn.f32x2 %0, %1, %2, %3;" : "=l"(d) : "l"(a), "l"(b), "l"(c));
    return d;
}
__device__ __forceinline__ ull pk2(float lo, float hi) {
    ull r; asm("mov.b64 %0, {%1, %2};" : "=l"(r) : "f"(lo), "f"(hi));
    return r;
}
__device__ __forceinline__ void up2(float& lo, float& hi, ull v) {
    asm("mov.b64 {%0, %1}, %2;" : "=f"(lo), "=f"(hi) : "l"(v));
}
__device__ __forceinline__ unsigned f2ord(float f) {
    unsigned b = __float_as_uint(f);
    return (b & 0x80000000u) ? ~b : (b | 0x80000000u);
}

// Stage tile: pack {x01,y01,z01,w01}, w = r^2 (reference rounding, no contraction).
__device__ __forceinline__ void stage_tile(ulonglong4* tile, const float* __restrict__ ref,
                                           int rbase) {
    for (int p = threadIdx.x; p < PPC; p += QPB) {
        const float2* a = (const float2*)(ref + (size_t)(rbase + 2 * p) * 3);
        float2 u0 = __ldg(a), u1 = __ldg(a + 1), u2 = __ldg(a + 2);
        float x0 = u0.x, y0 = u0.y, z0 = u1.x, x1 = u1.y, y1 = u2.x, z1 = u2.y;
        float w0 = __fadd_rn(__fadd_rn(__fmul_rn(x0, x0), __fmul_rn(y0, y0)), __fmul_rn(z0, z0));
        float w1 = __fadd_rn(__fadd_rn(__fmul_rn(x1, x1), __fmul_rn(y1, y1)), __fmul_rn(z1, z1));
        ulonglong4 v;
        v.x = pk2(x0, x1); v.y = pk2(y0, y1); v.z = pk2(z0, z1); v.w = pk2(w0, w1);
        tile[p] = v;
    }
}

// p1a: full scan; store the min of every 32-ref slice per query. Branchless.
__global__ __launch_bounds__(QPB) void knn_p1a(const float* __restrict__ qry,
                                               const float* __restrict__ ref) {
    __shared__ ulonglong4 tile[PPC];
    const int chunk = blockIdx.x % NCHUNK;
    const int qb    = (blockIdx.x / NCHUNK) * QPG + threadIdx.x;
    stage_tile(tile, ref, chunk * RPC);

    ull m2x[QT], m2y[QT], m2z[QT];
#pragma unroll
    for (int k = 0; k < QT; ++k) {
        int qi = qb + k * QPB;
        float qx = qry[qi * 3 + 0], qy = qry[qi * 3 + 1], qz = qry[qi * 3 + 2];
        m2x[k] = pk2(-2.0f * qx, -2.0f * qx);
        m2y[k] = pk2(-2.0f * qy, -2.0f * qy);
        m2z[k] = pk2(-2.0f * qz, -2.0f * qz);
    }
    const float INF = __int_as_float(0x7f800000);
    float sm[QT][NSL];
    __syncthreads();

#pragma unroll
    for (int sl = 0; sl < NSL; ++sl) {
        float a0[QT], a1[QT];
#pragma unroll
        for (int k = 0; k < QT; ++k) { a0[k] = INF; a1[k] = INF; }
        const ulonglong4* base = tile + sl * PPSL;
#pragma unroll
        for (int it = 0; it < PPSL; ++it) {
            ulonglong4 v = base[it];            // warp-uniform -> LDS broadcast
#pragma unroll
            for (int k = 0; k < QT; ++k) {
                ull s2 = fma2(m2x[k], v.x, fma2(m2y[k], v.y, fma2(m2z[k], v.z, v.w)));
                float s0, s1; up2(s0, s1, s2);
                a0[k] = fminf(a0[k], s0); a1[k] = fminf(a1[k], s1);
            }
        }
#pragma unroll
        for (int k = 0; k < QT; ++k) sm[k][sl] = fminf(a0[k], a1[k]);
    }

#pragma unroll
    for (int k = 0; k < QT; ++k) {
        int qi = qb + k * QPB;
        float4* dst = (float4*)(g_smin + (size_t)qi * NSLICES + chunk * NSL);
        dst[0] = make_float4(sm[k][0], sm[k][1], sm[k][2], sm[k][3]);
        dst[1] = make_float4(sm[k][4], sm[k][5], sm[k][6], sm[k][7]);
    }
}

// p1c: warp per query. tau = 8th-smallest per-lane slice-min (bitonic-32),
// bitmask+scan gate, gather hit slices, bitonic-32 merge of keys, write top-8.
__global__ __launch_bounds__(256) void knn_p1c(const float* __restrict__ qry,
                                               const float* __restrict__ ref,
                                               float* __restrict__ out) {
    __shared__ int sh_ids[8][MAXH];
    __shared__ ull sh_keys[8][MAXK];
    const int wid  = threadIdx.x >> 5;
    const int lane = threadIdx.x & 31;
    const int qi   = blockIdx.x * 8 + wid;

    // Load this lane's 16 slice minima (2 KB/warp, coalesced float4).
    const float4* sp = (const float4*)(g_smin + (size_t)qi * NSLICES + lane * 16);
    float v[16];
#pragma unroll
    for (int i = 0; i < 4; ++i) {
        float4 f = sp[i];
        v[i * 4 + 0] = f.x; v[i * 4 + 1] = f.y; v[i * 4 + 2] = f.z; v[i * 4 + 3] = f.w;
    }

    // Per-lane min of 16 (15 fmin).
    float pm = v[0];
#pragma unroll
    for (int j = 1; j < 16; ++j) pm = fminf(pm, v[j]);

    // Bitonic sort of 32 per-lane minima across lanes (ascending); tau = rank 7.
    // Valid conservative gate: 8 smallest per-lane minima = 8 distinct slices
    // = 8 distinct elements <= tau  =>  tau >= true 8th-smallest distance.
    float sv = pm;
#pragma unroll
    for (int k = 2; k <= 32; k <<= 1) {
#pragma unroll
        for (int j = k >> 1; j >= 1; j >>= 1) {
            float o = __shfl_xor_sync(0xffffffffu, sv, j);
            bool up      = ((lane & k) == 0);
            bool is_low  = ((lane & j) == 0);
            bool keepmin = (is_low == up);
            sv = keepmin ? fminf(sv, o) : fmaxf(sv, o);
        }
    }
    const float tau = __shfl_sync(0xffffffffu, sv, KNN - 1);

    // Gate: 16-bit hitmask per lane, warp scan, compact slice ids to smem.
    unsigned hm = 0;
#pragma unroll
    for (int j = 0; j < 16; ++j) hm |= (v[j] <= tau) ? (1u << j) : 0u;
    int cnt = __popc(hm);
    int inc = cnt;
#pragma unroll
    for (int d = 1; d < 32; d <<= 1) {
        int n = __shfl_up_sync(0xffffffffu, inc, d);
        if (lane >= d) inc += n;
    }
    int slot = inc - cnt;                       // exclusive prefix
    int nhit = __shfl_sync(0xffffffffu, inc, 31);
    unsigned mm = hm;
    while (mm) {
        int b = __ffs(mm) - 1;
        if (slot < MAXH) sh_ids[wid][slot] = lane * 16 + b;
        ++slot;
        mm &= mm - 1;
    }
    if (nhit > MAXH) nhit = MAXH;
    __syncwarp();

    // Query coefficients (scalar; bit-identical rounding to p1a's f32x2 lanes).
    const float qx = qry[qi * 3 + 0];
    const float qy = qry[qi * 3 + 1];
    const float qz = qry[qi * 3 + 2];
    const float m2x = -2.0f * qx, m2y = -2.0f * qy, m2z = -2.0f * qz;

    // Gather hit slices: 1 ref per lane per slice; collect keys with s <= tau.
    int nk = 0;
    for (int h = 0; h < nhit; ++h) {
        int s = sh_ids[wid][h];
        int ridx = s * 32 + lane;
        const float* rp = ref + (size_t)ridx * 3;
        float x = rp[0], y = rp[1], z = rp[2];
        float w = __fadd_rn(__fadd_rn(__fmul_rn(x, x), __fmul_rn(y, y)), __fmul_rn(z, z));
        float sd = __fmaf_rn(m2x, x, __fmaf_rn(m2y, y, __fmaf_rn(m2z, z, w)));
        bool p = (sd <= tau);
        unsigned m = __ballot_sync(0xffffffffu, p);
        int pre = __popc(m & ((1u << lane) - 1));
        int ks = nk + pre;
        if (p && ks < MAXK)
            sh_keys[wid][ks] = ((ull)f2ord(sd) << 32) | (unsigned)ridx;
        nk += __popc(m);
    }
    if (nk > MAXK) nk = MAXK;
    __syncwarp();

    // Merge: lane j takes key j (pad ~0), bitonic-32 sort on u64, lanes 0-7 emit.
    ull kv = (lane < nk) ? sh_keys[wid][lane] : ~0ull;
#pragma unroll
    for (int k = 2; k <= 32; k <<= 1) {
#pragma unroll
        for (int j = k >> 1; j >= 1; j >>= 1) {
            ull o = __shfl_xor_sync(0xffffffffu, kv, j);
            bool up      = ((lane & k) == 0);
            bool is_low  = ((lane & j) == 0);
            bool keepmin = (is_low == up);
            bool lt = (kv < o);
            kv = (keepmin == lt) ? kv : o;
        }
    }
    if (lane < KNN)
        out[qi * KNN + lane] = (float)(int)(kv & 0xffffffffu);
}

extern "C" void kernel_launch(void* const* d_in, const int* in_sizes, int n_in,
                              void* d_out, int out_size) {
    (void)n_in; (void)out_size;
    const float* q;
    const float* r;
    if (in_sizes[0] < in_sizes[1]) { q = (const float*)d_in[0]; r = (const float*)d_in[1]; }
    else                           { q = (const float*)d_in[1]; r = (const float*)d_in[0]; }

    knn_p1a<<<QBLK * NCHUNK, QPB>>>(q, r);
    knn_p1c<<<NQ / 8, 256>>>(q, r, (float*)d_out);
}